// round 16
// baseline (speedup 1.0000x reference)
#include <cuda_runtime.h>
#include <cuda_bf16.h>
#include <cstdint>

#define OPC 31
#define BB 64
#define DD 1024
#define NSTEP 16

// ---- tiling ----
#define NT 128                              // item n-width (2 x 64-wide B subtiles)
#define A_TILE 16384                        // 128 rows x 64 bf16 (128B rows, SW128)
#define B_SUB 8192                          // 64 k-rows x 64 n (128B rows, SW128)
#define STG_BYTES (A_TILE + 4 * B_SUB)      // 49152
#define NSTAGE 2
#define SMEM_STAGES (NSTAGE * STG_BYTES)    // 98304
#define MBAR_FULL   (SMEM_STAGES)           // 2 x 8B
#define MBAR_EMPTY  (SMEM_STAGES + 16)      // 2 x 8B
#define BC_OFF      (SMEM_STAGES + 32)
#define GEMM_SMEM   (SMEM_STAGES + 64)      // 98368 -> 2 CTAs/SM
#define NITEMS (OPC * (DD / NT))            // 248
#define NTHR 416                            // 12 consumer warps + 1 producer

#define SWZ(o) ((o) ^ (((o) >> 3) & 0x70))

// ---- scratch (device globals; no runtime allocation) ----
__device__ __align__(128) __nv_bfloat16 g_Bhi[(size_t)OPC * 16 * 16 * 4096];
__device__ __align__(128) __nv_bfloat16 g_Blo[(size_t)OPC * 16 * 16 * 4096];
__device__ __align__(128) __nv_bfloat16 g_Apk[16 * 8192];   // 16 chunks x 16KB
__device__ float g_Y[(size_t)OPC * BB * DD];
__device__ float g_h[BB * DD];
__device__ float g_W[NSTEP * BB * OPC];
__device__ float g_gate[NSTEP * BB];
__device__ int   g_ctr[NSTEP];

// ---- helpers ----
static __device__ __forceinline__ uint32_t sptr(const void* p) {
    return (uint32_t)__cvta_generic_to_shared(p);
}
static __device__ __forceinline__ void mbar_init(uint32_t bar, uint32_t cnt) {
    asm volatile("mbarrier.init.shared.b64 [%0], %1;" :: "r"(bar), "r"(cnt) : "memory");
}
static __device__ __forceinline__ void mbar_arrive(uint32_t bar) {
    asm volatile("mbarrier.arrive.shared.b64 _, [%0];" :: "r"(bar) : "memory");
}
static __device__ __forceinline__ void mbar_expect_tx(uint32_t bar, uint32_t bytes) {
    asm volatile("mbarrier.arrive.expect_tx.shared.b64 _, [%0], %1;"
                 :: "r"(bar), "r"(bytes) : "memory");
}
static __device__ __forceinline__ void mbar_wait_acq(uint32_t bar, uint32_t phase) {
    asm volatile(
        "{\n\t.reg .pred P;\n"
        "W_%=:\n\t"
        "mbarrier.try_wait.parity.acquire.cta.shared::cta.b64 P, [%0], %1, 0x989680;\n\t"
        "@P bra.uni D_%=;\n\t"
        "bra.uni W_%=;\n"
        "D_%=:\n\t}"
        :: "r"(bar), "r"(phase) : "memory");
}
static __device__ __forceinline__ void mbar_wait_rlx(uint32_t bar, uint32_t phase) {
    asm volatile(
        "{\n\t.reg .pred P;\n"
        "W_%=:\n\t"
        "mbarrier.try_wait.parity.relaxed.cta.shared::cta.b64 P, [%0], %1, 0x989680;\n\t"
        "@P bra.uni D_%=;\n\t"
        "bra.uni W_%=;\n"
        "D_%=:\n\t}"
        :: "r"(bar), "r"(phase) : "memory");
}
static __device__ __forceinline__ void bulkcp(uint32_t dst, const void* src,
                                              uint32_t bytes, uint32_t mbar) {
    asm volatile(
        "cp.async.bulk.shared::cluster.global.mbarrier::complete_tx::bytes "
        "[%0], [%1], %2, [%3];"
        :: "r"(dst), "l"(src), "r"(bytes), "r"(mbar) : "memory");
}
static __device__ __forceinline__ void ldsm_x4(uint32_t r[4], uint32_t addr) {
    asm volatile("ldmatrix.sync.aligned.m8n8.x4.shared.b16 {%0,%1,%2,%3}, [%4];"
                 : "=r"(r[0]), "=r"(r[1]), "=r"(r[2]), "=r"(r[3]) : "r"(addr));
}
static __device__ __forceinline__ void ldsm_x4_t(uint32_t r[4], uint32_t addr) {
    asm volatile("ldmatrix.sync.aligned.m8n8.x4.trans.shared.b16 {%0,%1,%2,%3}, [%4];"
                 : "=r"(r[0]), "=r"(r[1]), "=r"(r[2]), "=r"(r[3]) : "r"(addr));
}
static __device__ __forceinline__ void mma16816(float c[4], const uint32_t a[4],
                                                uint32_t b0, uint32_t b1) {
    asm volatile("mma.sync.aligned.m16n8k16.row.col.f32.bf16.bf16.f32 "
                 "{%0,%1,%2,%3}, {%4,%5,%6,%7}, {%8,%9}, {%0,%1,%2,%3};"
                 : "+f"(c[0]), "+f"(c[1]), "+f"(c[2]), "+f"(c[3])
                 : "r"(a[0]), "r"(a[1]), "r"(a[2]), "r"(a[3]), "r"(b0), "r"(b1));
}

// ============================================================================
// 1) Split op_kernels fp32 -> packed, pre-swizzled bf16 hi/lo [k][n] tiles.
//    Tile (o, nt64, kc): 64 k-rows x 64 n-cols, 128B rows, SW128. (R13-proven)
// ============================================================================
__global__ void convert_kernel(const float* __restrict__ K) {
    const size_t n4 = (size_t)OPC * DD * DD / 4;
    const float4* K4 = (const float4*)K;
    char* Bh = (char*)g_Bhi;
    char* Bl = (char*)g_Blo;
    for (size_t i = blockIdx.x * (size_t)blockDim.x + threadIdx.x; i < n4;
         i += (size_t)gridDim.x * blockDim.x) {
        int o = (int)(i / (DD * DD / 4));
        int rem = (int)(i % (DD * DD / 4));
        int d = rem >> 8;
        int n = (rem & 255) * 4;
        float4 v = K4[i];
        float x[4] = {v.x, v.y, v.z, v.w};
        unsigned short hi[4], lo[4];
#pragma unroll
        for (int j = 0; j < 4; ++j) {
            __nv_bfloat16 h = __float2bfloat16(x[j]);
            __nv_bfloat16 l = __float2bfloat16(x[j] - __bfloat162float(h));
            hi[j] = __bfloat16_as_ushort(h);
            lo[j] = __bfloat16_as_ushort(l);
        }
        uint2 ph, pl;
        ph.x = (uint32_t)hi[0] | ((uint32_t)hi[1] << 16);
        ph.y = (uint32_t)hi[2] | ((uint32_t)hi[3] << 16);
        pl.x = (uint32_t)lo[0] | ((uint32_t)lo[1] << 16);
        pl.y = (uint32_t)lo[2] | ((uint32_t)lo[3] << 16);
        int kc = d >> 6, kr = d & 63, nt = n >> 6, nc = n & 63;
        size_t tile = ((size_t)(o * 16 + nt) * 16 + kc) * B_SUB;
        uint32_t off = SWZ((uint32_t)(kr * 128 + nc * 2));
        *(uint2*)(Bh + tile + off) = ph;
        *(uint2*)(Bl + tile + off) = pl;
    }
}

// ============================================================================
// 2) Softmax + gates; zero tickets each replay.
// ============================================================================
__global__ void prep_kernel(const float* __restrict__ logits,
                            const float* __restrict__ operands) {
    if (blockIdx.x == 0 && threadIdx.x < NSTEP) g_ctr[threadIdx.x] = 0;
    int gw = (blockIdx.x * blockDim.x + threadIdx.x) >> 5;
    int lane = threadIdx.x & 31;
    if (gw >= BB * NSTEP) return;
    int b = gw >> 4, s = gw & 15;
    float x = (lane < OPC) ? logits[(b * 16 + s) * OPC + lane] : -INFINITY;
    float m = x;
#pragma unroll
    for (int d = 16; d; d >>= 1) m = fmaxf(m, __shfl_xor_sync(0xffffffffu, m, d));
    float e = (lane < OPC) ? expf(x - m) : 0.f;
    float sum = e;
#pragma unroll
    for (int d = 16; d; d >>= 1) sum += __shfl_xor_sync(0xffffffffu, sum, d);
    if (lane < OPC) g_W[((size_t)s * BB + b) * OPC + lane] = e / sum;
    if (lane == 0)
        g_gate[s * BB + b] = 1.f / (1.f + expf(-operands[(b * 16 + s) * 4 + 3]));
}

// ---- A-pack write: row b (hi) / row 64+b (lo), chunk kc, col c; swizzled ----
static __device__ __forceinline__ void write_Apk(int b, int k, float hval) {
    char* A = (char*)g_Apk;
    int kc = k >> 6, c = k & 63;
    __nv_bfloat16 hi = __float2bfloat16(hval);
    __nv_bfloat16 lo = __float2bfloat16(hval - __bfloat162float(hi));
    uint32_t off_hi = SWZ((uint32_t)(b * 128 + c * 2));
    uint32_t off_lo = SWZ((uint32_t)((64 + b) * 128 + c * 2));
    *(unsigned short*)(A + (size_t)kc * A_TILE + off_hi) = __bfloat16_as_ushort(hi);
    *(unsigned short*)(A + (size_t)kc * A_TILE + off_lo) = __bfloat16_as_ushort(lo);
}

// ============================================================================
// 3) h := signal; build packed A.
// ============================================================================
__global__ void init_kernel(const float* __restrict__ signal) {
    int idx = blockIdx.x * blockDim.x + threadIdx.x;
    if (idx >= BB * DD) return;
    float h = signal[idx];
    g_h[idx] = h;
    write_Apk(idx >> 10, idx & 1023, h);
}

// ============================================================================
// 4) Persistent bulk-copy GEMM, NT=128 items. 2 CTAs/SM.
//    Warp 12: producer (5 bulk copies / 48KB stage).
//    Warps 0-7 (P1): [h_hi;h_lo](128 x d) @ K_hi, 32x64 tiles.
//    Warps 8-11 (P2): h_hi(64 x d) @ K_lo, 32x64 tiles.
//    Stage: [A 16K][Bhi0 8K][Bhi1 8K][Blo0 8K][Blo1 8K].
//    Epilogue: 3-phase disjoint-row additive reduction into red[64][132].
// ============================================================================
__global__ void __launch_bounds__(NTHR, 2) step_gemm_kernel(int t) {
    extern __shared__ __align__(128) char smem[];
    const uint32_t sbase = sptr(smem);
    int* bc = (int*)(smem + BC_OFF);
    const int tid = threadIdx.x;
    const int w = tid >> 5, lane = tid & 31;

    if (tid == 0) {
#pragma unroll
        for (int s = 0; s < NSTAGE; ++s) {
            mbar_init(sbase + MBAR_FULL + s * 8, 1);    // expect_tx arrival
            mbar_init(sbase + MBAR_EMPTY + s * 8, 12);  // one per consumer warp
        }
    }
    __syncthreads();

    const bool isProd = (w == 12);
    const bool isP2 = (w >= 8) && !isProd;
    const int wl = isP2 ? (w - 8) : w;
    const int wm = (wl >> 1) * 32;      // P1: 0,32,64,96 ; P2: 0,32
    const int wn = (wl & 1) * 64;       // 0 or 64 -> one B subtile each
    const int lr = lane & 15;
    const int lc = (lane >> 4) * 8;
    const int rb = lane >> 2;
    const int cb = (lane & 3) * 2;

    // pipeline cursors (persist across items)
    int pst = 0; uint32_t pph = 1;      // producer over empty barriers
    int cst = 0; uint32_t cph = 0;      // consumers over full barriers

    // per-lane invariant byte offsets (pre-swizzle)
    const uint32_t aRow = (uint32_t)((wm + lr) * 128 + lc * 2);
    const uint32_t bRow = (uint32_t)(lr * 128 + lc * 2);
    const uint32_t bOff = (uint32_t)(A_TILE + (isP2 ? 2 * B_SUB : 0) +
                                     (wn >> 6) * B_SUB);

    for (;;) {
        if (tid == 0) *bc = atomicAdd(&g_ctr[t], 1);
        __syncthreads();
        const int item = *bc;
        __syncthreads();
        if (item >= NITEMS) break;

        const int o = item >> 3;
        const int ntp = item & 7;
        const char* gBh = (const char*)g_Bhi + (size_t)o * 16 * 16 * B_SUB;
        const char* gBl = (const char*)g_Blo + (size_t)o * 16 * 16 * B_SUB;
        const char* gA  = (const char*)g_Apk;

        float acc[2][8][4];
#pragma unroll
        for (int i = 0; i < 2; ++i)
#pragma unroll
            for (int j = 0; j < 8; ++j)
#pragma unroll
                for (int r = 0; r < 4; ++r) acc[i][j][r] = 0.f;

        if (isProd) {
            if (lane == 0) {
                for (int kc = 0; kc < 16; ++kc) {
                    uint32_t eb = sbase + MBAR_EMPTY + pst * 8;
                    uint32_t fb = sbase + MBAR_FULL + pst * 8;
                    mbar_wait_rlx(eb, pph);
                    mbar_expect_tx(fb, STG_BYTES);
                    uint32_t dst = sbase + pst * STG_BYTES;
                    bulkcp(dst, gA + (size_t)kc * A_TILE, A_TILE, fb);
#pragma unroll
                    for (int s = 0; s < 2; ++s) {
                        size_t toff = ((size_t)(2 * ntp + s) * 16 + kc) * B_SUB;
                        bulkcp(dst + A_TILE + s * B_SUB, gBh + toff, B_SUB, fb);
                        bulkcp(dst + A_TILE + 2 * B_SUB + s * B_SUB, gBl + toff,
                               B_SUB, fb);
                    }
                    if (++pst == NSTAGE) { pst = 0; pph ^= 1; }
                }
            }
        } else {
            for (int kc = 0; kc < 16; ++kc) {
                uint32_t fb = sbase + MBAR_FULL + cst * 8;
                mbar_wait_acq(fb, cph);
                uint32_t aB = sbase + cst * STG_BYTES;
                uint32_t bB = aB + bOff;
#pragma unroll
                for (int kb = 0; kb < 4; ++kb) {
                    uint32_t a[2][4];
#pragma unroll
                    for (int mi = 0; mi < 2; ++mi)
                        ldsm_x4(a[mi], aB + SWZ(aRow + mi * 2048 + kb * 32));
#pragma unroll
                    for (int nj = 0; nj < 4; ++nj) {
                        uint32_t b[4];
                        ldsm_x4_t(b, bB + SWZ(bRow + kb * 2048 + nj * 32));
                        mma16816(acc[0][nj * 2 + 0], a[0], b[0], b[1]);
                        mma16816(acc[0][nj * 2 + 1], a[0], b[2], b[3]);
                        mma16816(acc[1][nj * 2 + 0], a[1], b[0], b[1]);
                        mma16816(acc[1][nj * 2 + 1], a[1], b[2], b[3]);
                    }
                }
                __syncwarp();
                if (lane == 0) mbar_arrive(sbase + MBAR_EMPTY + cst * 8);
                if (++cst == NSTAGE) { cst = 0; cph ^= 1; }
            }
        }
        __syncthreads();   // all stage copies landed & consumed; smem reusable

        // ---- epilogue: 3-phase additive reduction, disjoint rows per phase ----
        float* red = (float*)smem;          // [64][132]
        if (!isProd && !isP2 && wm < 64) {  // phase 1: hi*Khi (write)
#pragma unroll
            for (int mi = 0; mi < 2; ++mi)
#pragma unroll
                for (int nj = 0; nj < 8; ++nj)
#pragma unroll
                    for (int r = 0; r < 4; ++r) {
                        int row = wm + mi * 16 + rb + ((r >> 1) << 3);
                        int col = wn + nj * 8 + cb + (r & 1);
                        red[row * 132 + col] = acc[mi][nj][r];
                    }
        }
        __syncthreads();
        if (!isProd && !isP2 && wm >= 64) { // phase 2: lo*Khi (add)
#pragma unroll
            for (int mi = 0; mi < 2; ++mi)
#pragma unroll
                for (int nj = 0; nj < 8; ++nj)
#pragma unroll
                    for (int r = 0; r < 4; ++r) {
                        int row = wm - 64 + mi * 16 + rb + ((r >> 1) << 3);
                        int col = wn + nj * 8 + cb + (r & 1);
                        red[row * 132 + col] += acc[mi][nj][r];
                    }
        }
        __syncthreads();
        if (isP2) {                         // phase 3: hi*Klo (add)
#pragma unroll
            for (int mi = 0; mi < 2; ++mi)
#pragma unroll
                for (int nj = 0; nj < 8; ++nj)
#pragma unroll
                    for (int r = 0; r < 4; ++r) {
                        int row = wm + mi * 16 + rb + ((r >> 1) << 3);
                        int col = wn + nj * 8 + cb + (r & 1);
                        red[row * 132 + col] += acc[mi][nj][r];
                    }
        }
        __syncthreads();

        float* Yo = g_Y + (size_t)o * BB * DD + ntp * NT;
        for (int id = tid; id < BB * NT; id += NTHR) {
            int b = id >> 7, n = id & 127;
            Yo[(size_t)b * DD + n] = red[b * 132 + n];
        }
        __syncthreads();   // red fully read before next item's bulk fills
    }
}

// ============================================================================
// 5) Per-step update: transformed = sum_o w*Y ; gate mix ; re-pack A.
// ============================================================================
__global__ void step_update_kernel(int t, float* __restrict__ out, int final_step) {
    int idx = blockIdx.x * blockDim.x + threadIdx.x;
    if (idx >= BB * DD) return;
    int b = idx >> 10, k = idx & 1023;
    const float* wrow = g_W + ((size_t)t * BB + b) * OPC;
    float tr = 0.f;
#pragma unroll
    for (int o2 = 0; o2 < OPC; ++o2)
        tr = fmaf(wrow[o2], g_Y[((size_t)o2 * BB + b) * DD + k], tr);
    float g = g_gate[t * BB + b];
    float h = g_h[idx];
    float hn = g * tr + (1.f - g) * h;
    if (final_step) out[idx] = hn;
    else            g_h[idx] = hn;
    write_Apk(b, k, hn);
}

// ============================================================================
// launch
// ============================================================================
extern "C" void kernel_launch(void* const* d_in, const int* in_sizes, int n_in,
                              void* d_out, int out_size) {
    const float* logits   = (const float*)d_in[0];
    const float* operands = (const float*)d_in[1];
    const float* signal   = (const float*)d_in[2];
    const float* opk      = (const float*)d_in[3];
    float* out = (float*)d_out;

    int nsm = 148;
    cudaDeviceGetAttribute(&nsm, cudaDevAttrMultiProcessorCount, 0);

    cudaFuncSetAttribute(step_gemm_kernel,
                         cudaFuncAttributeMaxDynamicSharedMemorySize, GEMM_SMEM);

    convert_kernel<<<4096, 256>>>(opk);
    prep_kernel<<<128, 256>>>(logits, operands);
    init_kernel<<<256, 256>>>(signal);
    for (int t = 0; t < NSTEP; ++t) {
        step_gemm_kernel<<<2 * nsm, NTHR, GEMM_SMEM>>>(t);
        step_update_kernel<<<256, 256>>>(t, out, (t == NSTEP - 1) ? 1 : 0);
    }
}

// round 17
// speedup vs baseline: 2.3601x; 2.3601x over previous
#include <cuda_runtime.h>
#include <cuda_bf16.h>
#include <cstdint>

#define OPC 31
#define BB 64
#define DD 1024
#define NSTEP 16

// ---- tiling (R13-proven) ----
#define NT 64
#define A_TILE 16384                       // 128 rows x 64 bf16 (128B rows, SW128)
#define B_TILE 8192                        // 64 k-rows x 64 n (128B rows, SW128)
#define STG_BYTES (A_TILE + 2 * B_TILE)    // 32768
#define NSTAGE 3
#define SMEM_STAGES (NSTAGE * STG_BYTES)   // 98304
#define MBAR_FULL  (SMEM_STAGES)           // 3 x 8B
#define MBAR_EMPTY (SMEM_STAGES + 24)      // 3 x 8B
#define BC_OFF     (SMEM_STAGES + 48)      // 2 x 4B ticket slots
#define GEMM_SMEM  (SMEM_STAGES + 64)      // 98368 -> 2 CTAs/SM
#define NITEMS (OPC * 16)                  // 496
#define NTHR 416                           // 12 consumer warps + 1 producer

#define SWZ(o) ((o) ^ (((o) >> 3) & 0x70))

// ---- scratch (device globals; no runtime allocation) ----
__device__ __align__(128) __nv_bfloat16 g_Bhi[(size_t)OPC * 16 * 16 * 4096];
__device__ __align__(128) __nv_bfloat16 g_Blo[(size_t)OPC * 16 * 16 * 4096];
__device__ __align__(128) __nv_bfloat16 g_Apk[16 * 8192];   // 16 chunks x 16KB
__device__ float g_Y1[(size_t)OPC * BB * DD];   // hi*Khi
__device__ float g_Y2[(size_t)OPC * BB * DD];   // lo*Khi
__device__ float g_Y3[(size_t)OPC * BB * DD];   // hi*Klo
__device__ float g_h[BB * DD];
__device__ float g_W[NSTEP * BB * OPC];
__device__ float g_gate[NSTEP * BB];
__device__ int   g_ctr[NSTEP];

// ---- helpers ----
static __device__ __forceinline__ uint32_t sptr(const void* p) {
    return (uint32_t)__cvta_generic_to_shared(p);
}
static __device__ __forceinline__ void mbar_init(uint32_t bar, uint32_t cnt) {
    asm volatile("mbarrier.init.shared.b64 [%0], %1;" :: "r"(bar), "r"(cnt) : "memory");
}
static __device__ __forceinline__ void mbar_arrive(uint32_t bar) {
    asm volatile("mbarrier.arrive.shared.b64 _, [%0];" :: "r"(bar) : "memory");
}
static __device__ __forceinline__ void mbar_expect_tx(uint32_t bar, uint32_t bytes) {
    asm volatile("mbarrier.arrive.expect_tx.shared.b64 _, [%0], %1;"
                 :: "r"(bar), "r"(bytes) : "memory");
}
static __device__ __forceinline__ void mbar_wait_acq(uint32_t bar, uint32_t phase) {
    asm volatile(
        "{\n\t.reg .pred P;\n"
        "W_%=:\n\t"
        "mbarrier.try_wait.parity.acquire.cta.shared::cta.b64 P, [%0], %1, 0x989680;\n\t"
        "@P bra.uni D_%=;\n\t"
        "bra.uni W_%=;\n"
        "D_%=:\n\t}"
        :: "r"(bar), "r"(phase) : "memory");
}
static __device__ __forceinline__ void mbar_wait_rlx(uint32_t bar, uint32_t phase) {
    asm volatile(
        "{\n\t.reg .pred P;\n"
        "W_%=:\n\t"
        "mbarrier.try_wait.parity.relaxed.cta.shared::cta.b64 P, [%0], %1, 0x989680;\n\t"
        "@P bra.uni D_%=;\n\t"
        "bra.uni W_%=;\n"
        "D_%=:\n\t}"
        :: "r"(bar), "r"(phase) : "memory");
}
static __device__ __forceinline__ void bulkcp(uint32_t dst, const void* src,
                                              uint32_t bytes, uint32_t mbar) {
    asm volatile(
        "cp.async.bulk.shared::cluster.global.mbarrier::complete_tx::bytes "
        "[%0], [%1], %2, [%3];"
        :: "r"(dst), "l"(src), "r"(bytes), "r"(mbar) : "memory");
}
static __device__ __forceinline__ void ldsm_x4(uint32_t r[4], uint32_t addr) {
    asm volatile("ldmatrix.sync.aligned.m8n8.x4.shared.b16 {%0,%1,%2,%3}, [%4];"
                 : "=r"(r[0]), "=r"(r[1]), "=r"(r[2]), "=r"(r[3]) : "r"(addr));
}
static __device__ __forceinline__ void ldsm_x4_t(uint32_t r[4], uint32_t addr) {
    asm volatile("ldmatrix.sync.aligned.m8n8.x4.trans.shared.b16 {%0,%1,%2,%3}, [%4];"
                 : "=r"(r[0]), "=r"(r[1]), "=r"(r[2]), "=r"(r[3]) : "r"(addr));
}
static __device__ __forceinline__ void mma16816(float c[4], const uint32_t a[4],
                                                uint32_t b0, uint32_t b1) {
    asm volatile("mma.sync.aligned.m16n8k16.row.col.f32.bf16.bf16.f32 "
                 "{%0,%1,%2,%3}, {%4,%5,%6,%7}, {%8,%9}, {%0,%1,%2,%3};"
                 : "+f"(c[0]), "+f"(c[1]), "+f"(c[2]), "+f"(c[3])
                 : "r"(a[0]), "r"(a[1]), "r"(a[2]), "r"(a[3]), "r"(b0), "r"(b1));
}

// ============================================================================
// 1) Split op_kernels fp32 -> packed, pre-swizzled bf16 hi/lo [k][n] tiles.
//    Tile (o, nt, kc): 64 k-rows x 64 n-cols, 128B rows, SW128. (R13-proven)
// ============================================================================
__global__ void convert_kernel(const float* __restrict__ K) {
    const size_t n4 = (size_t)OPC * DD * DD / 4;
    const float4* K4 = (const float4*)K;
    char* Bh = (char*)g_Bhi;
    char* Bl = (char*)g_Blo;
    for (size_t i = blockIdx.x * (size_t)blockDim.x + threadIdx.x; i < n4;
         i += (size_t)gridDim.x * blockDim.x) {
        int o = (int)(i / (DD * DD / 4));
        int rem = (int)(i % (DD * DD / 4));
        int d = rem >> 8;
        int n = (rem & 255) * 4;
        float4 v = K4[i];
        float x[4] = {v.x, v.y, v.z, v.w};
        unsigned short hi[4], lo[4];
#pragma unroll
        for (int j = 0; j < 4; ++j) {
            __nv_bfloat16 h = __float2bfloat16(x[j]);
            __nv_bfloat16 l = __float2bfloat16(x[j] - __bfloat162float(h));
            hi[j] = __bfloat16_as_ushort(h);
            lo[j] = __bfloat16_as_ushort(l);
        }
        uint2 ph, pl;
        ph.x = (uint32_t)hi[0] | ((uint32_t)hi[1] << 16);
        ph.y = (uint32_t)hi[2] | ((uint32_t)hi[3] << 16);
        pl.x = (uint32_t)lo[0] | ((uint32_t)lo[1] << 16);
        pl.y = (uint32_t)lo[2] | ((uint32_t)lo[3] << 16);
        int kc = d >> 6, kr = d & 63, nt = n >> 6, nc = n & 63;
        size_t tile = ((size_t)(o * 16 + nt) * 16 + kc) * B_TILE;
        uint32_t off = SWZ((uint32_t)(kr * 128 + nc * 2));
        *(uint2*)(Bh + tile + off) = ph;
        *(uint2*)(Bl + tile + off) = pl;
    }
}

// ============================================================================
// 2) Softmax + gates; zero tickets each replay.
// ============================================================================
__global__ void prep_kernel(const float* __restrict__ logits,
                            const float* __restrict__ operands) {
    if (blockIdx.x == 0 && threadIdx.x < NSTEP) g_ctr[threadIdx.x] = 0;
    int gw = (blockIdx.x * blockDim.x + threadIdx.x) >> 5;
    int lane = threadIdx.x & 31;
    if (gw >= BB * NSTEP) return;
    int b = gw >> 4, s = gw & 15;
    float x = (lane < OPC) ? logits[(b * 16 + s) * OPC + lane] : -INFINITY;
    float m = x;
#pragma unroll
    for (int d = 16; d; d >>= 1) m = fmaxf(m, __shfl_xor_sync(0xffffffffu, m, d));
    float e = (lane < OPC) ? expf(x - m) : 0.f;
    float sum = e;
#pragma unroll
    for (int d = 16; d; d >>= 1) sum += __shfl_xor_sync(0xffffffffu, sum, d);
    if (lane < OPC) g_W[((size_t)s * BB + b) * OPC + lane] = e / sum;
    if (lane == 0)
        g_gate[s * BB + b] = 1.f / (1.f + expf(-operands[(b * 16 + s) * 4 + 3]));
}

// ---- A-pack write: row b (hi) / row 64+b (lo), chunk kc, col c; swizzled ----
static __device__ __forceinline__ void write_Apk(int b, int k, float hval) {
    char* A = (char*)g_Apk;
    int kc = k >> 6, c = k & 63;
    __nv_bfloat16 hi = __float2bfloat16(hval);
    __nv_bfloat16 lo = __float2bfloat16(hval - __bfloat162float(hi));
    uint32_t off_hi = SWZ((uint32_t)(b * 128 + c * 2));
    uint32_t off_lo = SWZ((uint32_t)((64 + b) * 128 + c * 2));
    *(unsigned short*)(A + (size_t)kc * A_TILE + off_hi) = __bfloat16_as_ushort(hi);
    *(unsigned short*)(A + (size_t)kc * A_TILE + off_lo) = __bfloat16_as_ushort(lo);
}

// ============================================================================
// 3) h := signal; build packed A.
// ============================================================================
__global__ void init_kernel(const float* __restrict__ signal) {
    int idx = blockIdx.x * blockDim.x + threadIdx.x;
    if (idx >= BB * DD) return;
    float h = signal[idx];
    g_h[idx] = h;
    write_Apk(idx >> 10, idx & 1023, h);
}

// ============================================================================
// 4) Persistent bulk-copy GEMM (R13 mainloop) with continuous pipeline:
//    - one __syncthreads per item (double-buffered ticket slot)
//    - epilogue = direct float2 stores of register fragments to Y1/Y2/Y3
//      (no smem reduction; stage buffers never overwritten -> no drain)
// ============================================================================
__global__ void __launch_bounds__(NTHR, 2) step_gemm_kernel(int t) {
    extern __shared__ __align__(128) char smem[];
    const uint32_t sbase = sptr(smem);
    int* bc = (int*)(smem + BC_OFF);     // [2] ticket slots
    const int tid = threadIdx.x;
    const int w = tid >> 5, lane = tid & 31;

    if (tid == 0) {
#pragma unroll
        for (int s = 0; s < NSTAGE; ++s) {
            mbar_init(sbase + MBAR_FULL + s * 8, 1);    // expect_tx arrival
            mbar_init(sbase + MBAR_EMPTY + s * 8, 12);  // one per consumer warp
        }
    }
    __syncthreads();

    const bool isProd = (w == 12);
    const bool isP2 = (w >= 8) && !isProd;
    const int wl = isP2 ? (w - 8) : w;
    const int wm = (wl >> 1) * 32;      // P1: 0,32,64,96 ; P2: 0,32
    const int wn = (wl & 1) * 32;
    const int lr = lane & 15;
    const int lc = (lane >> 4) * 8;
    const int rb = lane >> 2;
    const int cb = (lane & 3) * 2;

    // pipeline cursors (persist across items; stage stream is continuous)
    int pst = 0; uint32_t pph = 1;      // producer over empty barriers
    int cst = 0; uint32_t cph = 0;      // consumers over full barriers

    // per-lane invariant byte offsets (pre-swizzle)
    const uint32_t aRow = (uint32_t)((wm + lr) * 128 + lc * 2);
    const uint32_t bRow = (uint32_t)(lr * 128 + (wn + lc) * 2);

    // destination partial-product buffer and row base for this warp
    float* Ybase = isP2 ? g_Y3 : (wm < 64 ? g_Y1 : g_Y2);
    const int rowb = (isP2 ? wm : (wm < 64 ? wm : wm - 64)) + rb;

    int iter = 0;
    for (;;) {
        if (tid == 0) bc[iter & 1] = atomicAdd(&g_ctr[t], 1);
        __syncthreads();                 // the ONLY per-item CTA sync
        const int item = bc[iter & 1];
        ++iter;
        if (item >= NITEMS) break;

        const int o = item >> 4;
        const int nt = item & 15;

        if (isProd) {
            if (lane == 0) {
                const char* gBh =
                    (const char*)g_Bhi + ((size_t)(o * 16 + nt) * 16) * B_TILE;
                const char* gBl =
                    (const char*)g_Blo + ((size_t)(o * 16 + nt) * 16) * B_TILE;
                const char* gA = (const char*)g_Apk;
                for (int kc = 0; kc < 16; ++kc) {
                    uint32_t eb = sbase + MBAR_EMPTY + pst * 8;
                    uint32_t fb = sbase + MBAR_FULL + pst * 8;
                    mbar_wait_rlx(eb, pph);
                    mbar_expect_tx(fb, STG_BYTES);
                    uint32_t dst = sbase + pst * STG_BYTES;
                    bulkcp(dst,                   gA  + (size_t)kc * A_TILE, A_TILE, fb);
                    bulkcp(dst + A_TILE,          gBh + (size_t)kc * B_TILE, B_TILE, fb);
                    bulkcp(dst + A_TILE + B_TILE, gBl + (size_t)kc * B_TILE, B_TILE, fb);
                    if (++pst == NSTAGE) { pst = 0; pph ^= 1; }
                }
            }
        } else {
            float acc[2][4][4];
#pragma unroll
            for (int i = 0; i < 2; ++i)
#pragma unroll
                for (int j = 0; j < 4; ++j)
#pragma unroll
                    for (int r = 0; r < 4; ++r) acc[i][j][r] = 0.f;

            for (int kc = 0; kc < 16; ++kc) {
                uint32_t fb = sbase + MBAR_FULL + cst * 8;
                mbar_wait_acq(fb, cph);
                uint32_t aB = sbase + cst * STG_BYTES;
                uint32_t bB = aB + A_TILE + (isP2 ? B_TILE : 0);
#pragma unroll
                for (int kb = 0; kb < 4; ++kb) {
                    uint32_t a[2][4];
#pragma unroll
                    for (int mi = 0; mi < 2; ++mi)
                        ldsm_x4(a[mi], aB + SWZ(aRow + mi * 2048 + kb * 32));
#pragma unroll
                    for (int nj = 0; nj < 2; ++nj) {
                        uint32_t b[4];
                        ldsm_x4_t(b, bB + SWZ(bRow + kb * 2048 + nj * 32));
                        mma16816(acc[0][nj * 2 + 0], a[0], b[0], b[1]);
                        mma16816(acc[0][nj * 2 + 1], a[0], b[2], b[3]);
                        mma16816(acc[1][nj * 2 + 0], a[1], b[0], b[1]);
                        mma16816(acc[1][nj * 2 + 1], a[1], b[2], b[3]);
                    }
                }
                __syncwarp();
                if (lane == 0) mbar_arrive(sbase + MBAR_EMPTY + cst * 8);
                if (++cst == NSTAGE) { cst = 0; cph ^= 1; }
            }

            // ---- direct epilogue: fragment -> partial-product buffer ----
            float* Yo = Ybase + (size_t)o * BB * DD + nt * NT;
#pragma unroll
            for (int mi = 0; mi < 2; ++mi) {
                const int row = rowb + mi * 16;
#pragma unroll
                for (int nj = 0; nj < 4; ++nj) {
                    const int col = wn + nj * 8 + cb;
                    *(float2*)&Yo[(size_t)row * DD + col] =
                        make_float2(acc[mi][nj][0], acc[mi][nj][1]);
                    *(float2*)&Yo[(size_t)(row + 8) * DD + col] =
                        make_float2(acc[mi][nj][2], acc[mi][nj][3]);
                }
            }
        }
    }
}

// ============================================================================
// 5) Per-step update: transformed = sum_o w*(Y1+Y2+Y3) ; gate mix ; re-pack A.
// ============================================================================
__global__ void step_update_kernel(int t, float* __restrict__ out, int final_step) {
    int idx = blockIdx.x * blockDim.x + threadIdx.x;
    if (idx >= BB * DD) return;
    int b = idx >> 10, k = idx & 1023;
    const float* wrow = g_W + ((size_t)t * BB + b) * OPC;
    float tr = 0.f;
#pragma unroll
    for (int o2 = 0; o2 < OPC; ++o2) {
        size_t off = ((size_t)o2 * BB + b) * DD + k;
        float y = g_Y1[off] + g_Y2[off] + g_Y3[off];
        tr = fmaf(wrow[o2], y, tr);
    }
    float g = g_gate[t * BB + b];
    float h = g_h[idx];
    float hn = g * tr + (1.f - g) * h;
    if (final_step) out[idx] = hn;
    else            g_h[idx] = hn;
    write_Apk(b, k, hn);
}

// ============================================================================
// launch
// ============================================================================
extern "C" void kernel_launch(void* const* d_in, const int* in_sizes, int n_in,
                              void* d_out, int out_size) {
    const float* logits   = (const float*)d_in[0];
    const float* operands = (const float*)d_in[1];
    const float* signal   = (const float*)d_in[2];
    const float* opk      = (const float*)d_in[3];
    float* out = (float*)d_out;

    int nsm = 148;
    cudaDeviceGetAttribute(&nsm, cudaDevAttrMultiProcessorCount, 0);

    cudaFuncSetAttribute(step_gemm_kernel,
                         cudaFuncAttributeMaxDynamicSharedMemorySize, GEMM_SMEM);

    convert_kernel<<<4096, 256>>>(opk);
    prep_kernel<<<128, 256>>>(logits, operands);
    init_kernel<<<256, 256>>>(signal);
    for (int t = 0; t < NSTEP; ++t) {
        step_gemm_kernel<<<2 * nsm, NTHR, GEMM_SMEM>>>(t);
        step_update_kernel<<<256, 256>>>(t, out, (t == NSTEP - 1) ? 1 : 0);
    }
}